// round 2
// baseline (speedup 1.0000x reference)
#include <cuda_runtime.h>
#include <stdint.h>

#define NEG (-1e9f)
constexpr int B_   = 128;
constexpr int NPG  = 1024;
constexpr int N_   = B_ * NPG;
constexpr int D_   = 128;
constexpr int GD_  = 128;
constexpr int M_   = 24;
constexpr int MAXC = 512;
constexpr int G_   = 8;
constexpr int ND_  = 7;
constexpr int AT_  = 5;
constexpr int P_   = 28;

// Scratch (no allocation allowed in kernel_launch)
__device__ int   d_cube_node[B_ * MAXC];
__device__ int   d_group_node[B_ * G_];
__device__ float d_cm_gc[B_ * 128];   // per-batch global contribution + b1 (cube head)
__device__ float d_mn_gc[B_ * 128];   // per-batch global contribution + b1 (maneuver head)
__device__ int   d_mask_mode;         // 0 = uint8, 1 = int32, 2 = float32

__constant__ int c_IU[P_] = {0,0,0,0,0,0,0,1,1,1,1,1,1,2,2,2,2,2,3,3,3,3,4,4,4,5,5,6};
__constant__ int c_JU[P_] = {1,2,3,4,5,6,7,2,3,4,5,6,7,3,4,5,6,7,4,5,6,7,5,6,7,6,7,7};

// ---------------------------------------------------------------------------
// Mask dtype probe. action_type_mask is all-true by construction, so its first
// 4 bytes uniquely identify the storage dtype:
//   int32 ones   -> 0x00000001
//   float32 ones -> 0x3F800000
//   uint8 ones   -> 0x01010101
// ---------------------------------------------------------------------------
__global__ void probe_mask_kernel(const int* __restrict__ atm_raw) {
    int v = atm_raw[0];
    int mode = 0;
    if (v == 1) mode = 1;
    else if (v == 0x3F800000) mode = 2;
    d_mask_mode = mode;
}

__device__ __forceinline__ bool read_mask(const void* p, long i) {
    int mode = d_mask_mode;
    if (mode == 1) return ((const int*)p)[i] != 0;
    if (mode == 2) return ((const float*)p)[i] != 0.f;
    return ((const uint8_t*)p)[i] != 0;
}

// ---------------------------------------------------------------------------
// Index building: per-batch exclusive running position of masked nodes
// (matches reference _seg_pos for contiguous batch segments).
// ---------------------------------------------------------------------------
__global__ void init_idx_kernel() {
    int t = blockIdx.x * blockDim.x + threadIdx.x;
    if (t < B_ * MAXC) d_cube_node[t] = -1;
    if (t < B_ * G_)   d_group_node[t] = -1;
}

__global__ void build_idx_kernel(const void* __restrict__ cube_mask,
                                 const void* __restrict__ group_mask) {
    int warp = (blockIdx.x * blockDim.x + threadIdx.x) >> 5;
    int lane = threadIdx.x & 31;
    if (warp >= B_) return;
    int base = warp * NPG;
    int cc = 0, gc = 0;
    for (int c = 0; c < NPG; c += 32) {
        long node = base + c + lane;
        bool cm = read_mask(cube_mask, node);
        bool gm = read_mask(group_mask, node);
        unsigned cb = __ballot_sync(0xffffffffu, cm);
        unsigned gb = __ballot_sync(0xffffffffu, gm);
        unsigned lt = (1u << lane) - 1u;
        if (cm) { int p = cc + __popc(cb & lt); if (p < MAXC) d_cube_node[warp * MAXC + p] = (int)node; }
        if (gm) { int p = gc + __popc(gb & lt); if (p < G_)   d_group_node[warp * G_ + p] = (int)node; }
        cc += __popc(cb);
        gc += __popc(gb);
    }
}

// ---------------------------------------------------------------------------
// Per-batch global contribution: out[b][h] = b1[h] + sum_k global[b][k] * W1[128+k][h]
// which == 0 -> cube head, 1 -> maneuver head
// ---------------------------------------------------------------------------
__global__ __launch_bounds__(128) void gcontrib_kernel(const float* __restrict__ gf,
                                                       const float* __restrict__ W1,
                                                       const float* __restrict__ b1,
                                                       int which) {
    int b = blockIdx.x;
    int h = threadIdx.x;
    __shared__ float g[GD_];
    g[h] = gf[b * GD_ + h];
    __syncthreads();
    float s = b1[h];
    #pragma unroll 4
    for (int k = 0; k < GD_; k++) s = fmaf(g[k], W1[(128 + k) * 128 + h], s);
    float* outp = which ? d_mn_gc : d_cm_gc;
    outp[b * 128 + h] = s;
}

// ---------------------------------------------------------------------------
// ActionTypeHead: [B,GD] -> 64 -> 5
// ---------------------------------------------------------------------------
__global__ __launch_bounds__(64) void at_kernel(const float* __restrict__ gf,
                                                const void* __restrict__ atm,
                                                const float* __restrict__ W1,
                                                const float* __restrict__ b1,
                                                const float* __restrict__ W2,
                                                const float* __restrict__ b2,
                                                float* __restrict__ out) {
    int b = blockIdx.x, t = threadIdx.x;
    __shared__ float g[GD_];
    __shared__ float h[64];
    g[t] = gf[b * GD_ + t];
    g[t + 64] = gf[b * GD_ + t + 64];
    __syncthreads();
    float s = b1[t];
    #pragma unroll 4
    for (int k = 0; k < GD_; k++) s = fmaf(g[k], W1[k * 64 + t], s);
    h[t] = fmaxf(s, 0.f);
    __syncthreads();
    if (t < AT_) {
        float s2 = b2[t];
        #pragma unroll 4
        for (int k = 0; k < 64; k++) s2 = fmaf(h[k], W2[k * AT_ + t], s2);
        out[b * AT_ + t] = read_mask(atm, b * AT_ + t) ? s2 : NEG;
    }
}

// ---------------------------------------------------------------------------
// CubeMoveHead: dominant fused GEMM.
// 64 rows per block (one row = (batch, slot)); hidden 128; out 24.
// ---------------------------------------------------------------------------
__global__ __launch_bounds__(256) void cube_kernel(const float* __restrict__ nodef,
                                                   const float* __restrict__ W1,
                                                   const float* __restrict__ W2,
                                                   const float* __restrict__ b2,
                                                   const void* __restrict__ move_mask,
                                                   float* __restrict__ out) {
    __shared__ union SM {
        struct { float Xs[64][33]; float Ws[32][128]; } p1;
        struct { float Hs[64][130]; float W2s[128][24]; float b2s[24]; } p2;
    } sm;
    __shared__ int   nodes[64];
    __shared__ float gc[128];

    int t = threadIdx.x;
    int row0 = blockIdx.x * 64;       // 64 divides MAXC -> block stays in one batch
    int b = row0 / MAXC;

    if (t < 64)  nodes[t] = d_cube_node[row0 + t];
    if (t < 128) gc[t] = d_cm_gc[b * 128 + t];
    __syncthreads();

    float acc[4][8];
    #pragma unroll
    for (int i = 0; i < 4; i++)
        #pragma unroll
        for (int j = 0; j < 8; j++) acc[i][j] = 0.f;

    int tr = t >> 4;       // 0..15 -> rows 4*tr..4*tr+3
    int tc = t & 15;       // 0..15 -> cols 8*tc..8*tc+7

    for (int k0 = 0; k0 < D_; k0 += 32) {
        #pragma unroll
        for (int i = 0; i < 8; i++) {          // X tile: 64x32
            int lin = t + i * 256;
            int r = lin >> 5, c = lin & 31;
            int node = nodes[r];
            sm.p1.Xs[r][c] = (node >= 0) ? nodef[(size_t)node * D_ + k0 + c] : 0.f;
        }
        #pragma unroll
        for (int i = 0; i < 16; i++) {         // W tile: 32x128
            int lin = t + i * 256;
            int r = lin >> 7, c = lin & 127;
            sm.p1.Ws[r][c] = W1[(k0 + r) * 128 + c];
        }
        __syncthreads();
        #pragma unroll
        for (int kk = 0; kk < 32; kk++) {
            float a0 = sm.p1.Xs[4 * tr + 0][kk];
            float a1 = sm.p1.Xs[4 * tr + 1][kk];
            float a2 = sm.p1.Xs[4 * tr + 2][kk];
            float a3 = sm.p1.Xs[4 * tr + 3][kk];
            #pragma unroll
            for (int j = 0; j < 8; j++) {
                float bv = sm.p1.Ws[kk][8 * tc + j];
                acc[0][j] = fmaf(a0, bv, acc[0][j]);
                acc[1][j] = fmaf(a1, bv, acc[1][j]);
                acc[2][j] = fmaf(a2, bv, acc[2][j]);
                acc[3][j] = fmaf(a3, bv, acc[3][j]);
            }
        }
        __syncthreads();
    }

    // bias(+global contribution) + relu -> Hs
    #pragma unroll
    for (int i = 0; i < 4; i++)
        #pragma unroll
        for (int j = 0; j < 8; j++) {
            float v = acc[i][j] + gc[8 * tc + j];
            sm.p2.Hs[4 * tr + i][8 * tc + j] = fmaxf(v, 0.f);
        }
    #pragma unroll
    for (int i = 0; i < 12; i++) {             // W2: 128x24 = 3072
        int lin = t + i * 256;
        sm.p2.W2s[lin / 24][lin % 24] = W2[lin];
    }
    if (t < 24) sm.p2.b2s[t] = b2[t];
    __syncthreads();

    // Second GEMM 64x128 @ 128x24, fused masking + write
    for (int idx = t; idx < 64 * M_; idx += 256) {
        int r = idx / M_;
        int m = idx - r * M_;
        float s = sm.p2.b2s[m];
        #pragma unroll 8
        for (int k = 0; k < 128; k++) s = fmaf(sm.p2.Hs[r][k], sm.p2.W2s[k][m], s);
        int gslot = row0 + r;                       // == b*MAXC + slot
        size_t o = (size_t)gslot * M_ + m;          // index into [B, MAXC, M]
        bool ok = (nodes[r] >= 0) && read_mask(move_mask, (long)o);
        out[o] = ok ? s : NEG;
    }
}

// ---------------------------------------------------------------------------
// DockingHead: one block per batch. h1 = relu(u[i] + v[j] + w), then 128->64->1.
// ---------------------------------------------------------------------------
__global__ __launch_bounds__(128) void dock_kernel(const float* __restrict__ nodef,
                                                   const float* __restrict__ gf,
                                                   const void* __restrict__ dvm,
                                                   const float* __restrict__ W1,
                                                   const float* __restrict__ b1,
                                                   const float* __restrict__ W2,
                                                   const float* __restrict__ b2,
                                                   const float* __restrict__ W3,
                                                   const float* __restrict__ b3,
                                                   float* __restrict__ out) {
    __shared__ float gf8[G_][D_];
    __shared__ float gl[GD_];
    __shared__ float u[G_][128];
    __shared__ float v[G_][128];
    __shared__ float w[128];
    __shared__ float W2s[128 * 64];
    __shared__ float h1[128];
    __shared__ float red[4];

    int b = blockIdx.x, t = threadIdx.x;

    #pragma unroll
    for (int g = 0; g < G_; g++) {
        int n = d_group_node[b * G_ + g];
        gf8[g][t] = (n >= 0) ? nodef[(size_t)n * D_ + t] : 0.f;
    }
    gl[t] = gf[b * GD_ + t];
    for (int i = 0; i < 64; i++) W2s[t + i * 128] = W2[t + i * 128];
    __syncthreads();

    // u[g] = gf8[g] @ W1[0:128], v[g] = gf8[g] @ W1[128:256], w = gl @ W1[256:384] + b1
    float uacc[G_], vacc[G_];
    #pragma unroll
    for (int g = 0; g < G_; g++) { uacc[g] = 0.f; vacc[g] = 0.f; }
    float wacc = b1[t];
    for (int k = 0; k < D_; k++) {
        float wa = W1[k * 128 + t];
        float wb = W1[(128 + k) * 128 + t];
        float wc = W1[(256 + k) * 128 + t];
        #pragma unroll
        for (int g = 0; g < G_; g++) {
            uacc[g] = fmaf(gf8[g][k], wa, uacc[g]);
            vacc[g] = fmaf(gf8[g][k], wb, vacc[g]);
        }
        wacc = fmaf(gl[k], wc, wacc);
    }
    #pragma unroll
    for (int g = 0; g < G_; g++) { u[g][t] = uacc[g]; v[g][t] = vacc[g]; }
    w[t] = wacc;
    __syncthreads();

    float W3t = (t < 64) ? W3[t] : 0.f;
    for (int p = 0; p < P_; p++) {
        int i = c_IU[p], j = c_JU[p];
        h1[t] = fmaxf(u[i][t] + v[j][t] + w[t], 0.f);
        __syncthreads();
        float s2 = 0.f;
        if (t < 64) {
            s2 = b2[t];
            #pragma unroll 8
            for (int k = 0; k < 128; k++) s2 = fmaf(h1[k], W2s[k * 64 + t], s2);
            s2 = fmaxf(s2, 0.f) * W3t;
        }
        #pragma unroll
        for (int off = 16; off; off >>= 1) s2 += __shfl_down_sync(0xffffffffu, s2, off);
        if ((t & 31) == 0 && t < 64) red[t >> 5] = s2;
        __syncthreads();
        if (t == 0) {
            int ni = d_group_node[b * G_ + i];
            int nj = d_group_node[b * G_ + j];
            bool ok = read_mask(dvm, b * P_ + p) && (ni >= 0) && (nj >= 0);
            out[b * P_ + p] = ok ? (red[0] + red[1] + b3[0]) : NEG;
        }
        __syncthreads();
    }
}

// ---------------------------------------------------------------------------
// ManeuverHead: one block per batch. 256 -> 128 -> 7 per group.
// ---------------------------------------------------------------------------
__global__ __launch_bounds__(128) void man_kernel(const float* __restrict__ nodef,
                                                  const void* __restrict__ mvm,
                                                  const float* __restrict__ W1,
                                                  const float* __restrict__ W2,
                                                  const float* __restrict__ b2,
                                                  float* __restrict__ out) {
    __shared__ float gf8[G_][D_];
    __shared__ float H[G_][128];
    __shared__ float W2s[128 * ND_];
    int b = blockIdx.x, t = threadIdx.x;

    #pragma unroll
    for (int g = 0; g < G_; g++) {
        int n = d_group_node[b * G_ + g];
        gf8[g][t] = (n >= 0) ? nodef[(size_t)n * D_ + t] : 0.f;
    }
    #pragma unroll
    for (int i = 0; i < ND_; i++) W2s[t + i * 128] = W2[t + i * 128];
    __syncthreads();

    float gc = d_mn_gc[b * 128 + t];
    float acc[G_];
    #pragma unroll
    for (int g = 0; g < G_; g++) acc[g] = gc;
    for (int k = 0; k < D_; k++) {
        float wa = W1[k * 128 + t];
        #pragma unroll
        for (int g = 0; g < G_; g++) acc[g] = fmaf(gf8[g][k], wa, acc[g]);
    }
    #pragma unroll
    for (int g = 0; g < G_; g++) H[g][t] = fmaxf(acc[g], 0.f);
    __syncthreads();

    if (t < G_ * ND_) {
        int g = t / ND_, d = t - g * ND_;
        float s = b2[d];
        #pragma unroll 8
        for (int k = 0; k < 128; k++) s = fmaf(H[g][k], W2s[k * ND_ + d], s);
        int n = d_group_node[b * G_ + g];
        bool ok = (n >= 0) && read_mask(mvm, b * G_ * ND_ + t);
        out[b * G_ * ND_ + t] = ok ? s : NEG;
    }
}

// ---------------------------------------------------------------------------
extern "C" void kernel_launch(void* const* d_in, const int* in_sizes, int n_in,
                              void* d_out, int out_size) {
    const float* nodef      = (const float*)d_in[0];
    const float* gf         = (const float*)d_in[1];
    const void*  atm        = d_in[2];
    const void*  cube_mask  = d_in[3];
    const void*  group_mask = d_in[4];
    /* d_in[5] = batch (unused; segments are contiguous) */
    const void*  move_mask  = d_in[6];
    const void*  dvm        = d_in[7];
    const void*  mvm        = d_in[8];
    const float* at_W1 = (const float*)d_in[9];
    const float* at_b1 = (const float*)d_in[10];
    const float* at_W2 = (const float*)d_in[11];
    const float* at_b2 = (const float*)d_in[12];
    const float* cm_W1 = (const float*)d_in[13];
    const float* cm_b1 = (const float*)d_in[14];
    const float* cm_W2 = (const float*)d_in[15];
    const float* cm_b2 = (const float*)d_in[16];
    const float* dk_W1 = (const float*)d_in[17];
    const float* dk_b1 = (const float*)d_in[18];
    const float* dk_W2 = (const float*)d_in[19];
    const float* dk_b2 = (const float*)d_in[20];
    const float* dk_W3 = (const float*)d_in[21];
    const float* dk_b3 = (const float*)d_in[22];
    const float* mn_W1 = (const float*)d_in[23];
    const float* mn_b1 = (const float*)d_in[24];
    const float* mn_W2 = (const float*)d_in[25];
    const float* mn_b2 = (const float*)d_in[26];

    float* out      = (float*)d_out;
    float* out_at   = out;
    float* out_cube = out + (size_t)B_ * AT_;
    float* out_dock = out_cube + (size_t)B_ * MAXC * M_;
    float* out_man  = out_dock + (size_t)B_ * P_;

    probe_mask_kernel<<<1, 1>>>((const int*)atm);
    init_idx_kernel<<<(B_ * MAXC + 255) / 256, 256>>>();
    build_idx_kernel<<<(B_ * 32 + 255) / 256, 256>>>(cube_mask, group_mask);

    gcontrib_kernel<<<B_, 128>>>(gf, cm_W1, cm_b1, 0);
    gcontrib_kernel<<<B_, 128>>>(gf, mn_W1, mn_b1, 1);

    at_kernel<<<B_, 64>>>(gf, atm, at_W1, at_b1, at_W2, at_b2, out_at);
    cube_kernel<<<(B_ * MAXC) / 64, 256>>>(nodef, cm_W1, cm_W2, cm_b2, move_mask, out_cube);
    dock_kernel<<<B_, 128>>>(nodef, gf, dvm, dk_W1, dk_b1, dk_W2, dk_b2, dk_W3, dk_b3, out_dock);
    man_kernel<<<B_, 128>>>(nodef, mvm, mn_W1, mn_W2, mn_b2, out_man);
}